// round 11
// baseline (speedup 1.0000x reference)
#include <cuda_runtime.h>
#include <cuda_fp16.h>
#include <cuda_bf16.h>

// dense_image_warp, B=8 H=1024 W=768 C=3 fp32.
// R11: R10 pipeline + cache-policy fixes.
//  - Streaming (never-reused) traffic uses evict-first: image __ldcs,
//    flow __ldcs, out __stcs -> stops polluting L2.
//  - g_pair stays cache-normal: with 1-batch chunks (12.5MB), the chunk
//    written by pad in launch k is still L2-resident when warp gathers it in
//    launch k+1 -> gathers hit L2 instead of DRAM.
//  - 8 chunks of 1 batch: smaller fill/drain ends, better residency.

#define WB 8
#define WH 1024
#define WW 768
#define PLANE (WH * WW)              // 786,432
#define NPIX (WB * PLANE)            // 6,291,456
#define THREADS 256
#define CHUNK_PX PLANE               // 1 batch per pipeline stage
#define CHUNK_BLK (CHUNK_PX / THREADS)   // 3072 blocks per role per stage

__device__ __align__(16) uint4 g_pair[NPIX];   // ~100.7 MB module-static scratch

__device__ __forceinline__ float2 h2f(unsigned u) {
    __half2 h = *reinterpret_cast<__half2*>(&u);
    return __half22float2(h);
}

// ---- role bodies (R5 bodies + cache hints) ----

__device__ __forceinline__ void pad_body(const float* __restrict__ img, int i)
{
    const float* p = img + 3ull * (unsigned)i;
    float r0 = __ldcs(p);
    float g0 = __ldcs(p + 1);
    float b0 = __ldcs(p + 2);

    int j = (i + 1 < NPIX) ? (i + 1) : i;
    const float* q = img + 3ull * (unsigned)j;
    float r1 = __ldcs(q);
    float g1 = __ldcs(q + 1);
    float b1 = __ldcs(q + 2);

    __half2 h0 = __floats2half2_rn(r0, g0);
    __half2 h1 = __floats2half2_rn(b0, r1);
    __half2 h2 = __floats2half2_rn(g1, b1);

    uint4 v;
    v.x = *reinterpret_cast<unsigned*>(&h0);
    v.y = *reinterpret_cast<unsigned*>(&h1);
    v.z = *reinterpret_cast<unsigned*>(&h2);
    v.w = 0u;
    g_pair[i] = v;          // cache-normal: next launch's warp reads this from L2
}

__device__ __forceinline__ void warp_body(const float* __restrict__ flow,
                                          float* __restrict__ out, int idx)
{
    int x = idx % WW;
    int t = idx / WW;
    int y = t & (WH - 1);
    int b = t >> 10;

    float2 f = __ldcs(reinterpret_cast<const float2*>(flow) + idx);
    float qy = (float)y - f.x;   // flow[...,0] = dy
    float qx = (float)x - f.y;   // flow[...,1] = dx

    float y0f = fminf(fmaxf(floorf(qy), 0.0f), (float)(WH - 2));
    float x0f = fminf(fmaxf(floorf(qx), 0.0f), (float)(WW - 2));
    float ay = fminf(fmaxf(qy - y0f, 0.0f), 1.0f);
    float ax = fminf(fmaxf(qx - x0f, 0.0f), 1.0f);

    const uint4* base = g_pair + ((size_t)b * PLANE + (int)y0f * WW + (int)x0f);
    uint4 top = __ldg(base);         // taps (y0,x0),(y0,x0+1)  — cache-normal
    uint4 bot = __ldg(base + WW);    // taps (y0+1,x0),(y0+1,x0+1)

    float2 t0 = h2f(top.x);
    float2 t1 = h2f(top.y);
    float2 t2 = h2f(top.z);
    float2 b0v = h2f(bot.x);
    float2 b1v = h2f(bot.y);
    float2 b2v = h2f(bot.z);

    float topr = t0.x + ax * (t1.y - t0.x);
    float topg = t0.y + ax * (t2.x - t0.y);
    float topb = t1.x + ax * (t2.y - t1.x);
    float botr = b0v.x + ax * (b1v.y - b0v.x);
    float botg = b0v.y + ax * (b2v.x - b0v.y);
    float botb = b1v.x + ax * (b2v.y - b1v.x);

    float* o = out + (size_t)idx * 3;
    __stcs(o + 0, topr + ay * (botr - topr));
    __stcs(o + 1, topg + ay * (botg - topg));
    __stcs(o + 2, topb + ay * (botb - topb));
}

// ---- launch wrappers ----

__global__ void __launch_bounds__(256) pad_stage(const float* __restrict__ img,
                                                 int base)
{
    int i = base + blockIdx.x * blockDim.x + threadIdx.x;
    pad_body(img, i);
}

__global__ void __launch_bounds__(256) warp_stage(const float* __restrict__ flow,
                                                  float* __restrict__ out,
                                                  int base)
{
    int i = base + blockIdx.x * blockDim.x + threadIdx.x;
    warp_body(flow, out, i);
}

// mix: even blocks warp chunk s, odd blocks pad chunk s+1.
__global__ void __launch_bounds__(256) mix_stage(const float* __restrict__ img,
                                                 const float* __restrict__ flow,
                                                 float* __restrict__ out,
                                                 int pad_base, int warp_base)
{
    int sub = (blockIdx.x >> 1) * blockDim.x + threadIdx.x;
    if (blockIdx.x & 1) {
        pad_body(img, pad_base + sub);
    } else {
        warp_body(flow, out, warp_base + sub);
    }
}

extern "C" void kernel_launch(void* const* d_in, const int* in_sizes, int n_in,
                              void* d_out, int out_size)
{
    const float* image = (const float*)d_in[0];
    const float* flow  = (const float*)d_in[1];
    float* out = (float*)d_out;

    // pipeline over 8 one-batch chunks
    pad_stage<<<CHUNK_BLK, THREADS>>>(image, 0);
    for (int s = 0; s < 7; s++) {
        mix_stage<<<2 * CHUNK_BLK, THREADS>>>(image, flow, out,
                                              (s + 1) * CHUNK_PX, s * CHUNK_PX);
    }
    warp_stage<<<CHUNK_BLK, THREADS>>>(flow, out, 7 * CHUNK_PX);
}

// round 12
// speedup vs baseline: 1.1115x; 1.1115x over previous
#include <cuda_runtime.h>
#include <cuda_fp16.h>
#include <cuda_bf16.h>

// dense_image_warp, B=8 H=1024 W=768 C=3 fp32.
// R12: exact R5 serial structure (champion, 88.5us) + cache-policy hints:
//   - flow reads  __ldcs  (zero reuse -> evict-first, stop polluting L2)
//   - out  writes __stcs  (zero reuse -> evict-first)
//   - g_pair gathers stay cache-normal (real ~2x reuse) -> more L2 room
// Everything else byte-identical to R5.

#define WB 8
#define WH 1024
#define WW 768
#define NPIX (WB * WH * WW)          // 6,291,456

__device__ __align__(16) uint4 g_pair[NPIX];   // ~100.7 MB module-static scratch

__device__ __forceinline__ float2 h2f(unsigned u) {
    __half2 h = *reinterpret_cast<__half2*>(&u);
    return __half22float2(h);
}

__global__ void __launch_bounds__(256) pad_pair_kernel(const float* __restrict__ img)
{
    int i = blockIdx.x * blockDim.x + threadIdx.x;
    if (i >= NPIX) return;

    const float* p = img + 3ull * (unsigned)i;
    float r0 = __ldg(p);
    float g0 = __ldg(p + 1);
    float b0 = __ldg(p + 2);

    int j = (i + 1 < NPIX) ? (i + 1) : i;
    const float* q = img + 3ull * (unsigned)j;
    float r1 = __ldg(q);
    float g1 = __ldg(q + 1);
    float b1 = __ldg(q + 2);

    __half2 h0 = __floats2half2_rn(r0, g0);
    __half2 h1 = __floats2half2_rn(b0, r1);
    __half2 h2 = __floats2half2_rn(g1, b1);

    uint4 v;
    v.x = *reinterpret_cast<unsigned*>(&h0);
    v.y = *reinterpret_cast<unsigned*>(&h1);
    v.z = *reinterpret_cast<unsigned*>(&h2);
    v.w = 0u;
    g_pair[i] = v;
}

__global__ void __launch_bounds__(256) warp_kernel(
    const float* __restrict__ flow,
    float* __restrict__ out)
{
    int idx = blockIdx.x * blockDim.x + threadIdx.x;
    if (idx >= NPIX) return;

    int x = idx % WW;
    int t = idx / WW;
    int y = t & (WH - 1);
    int b = t >> 10;

    float2 f = __ldcs(reinterpret_cast<const float2*>(flow) + idx);  // streaming
    float qy = (float)y - f.x;   // flow[...,0] = dy
    float qx = (float)x - f.y;   // flow[...,1] = dx

    float y0f = fminf(fmaxf(floorf(qy), 0.0f), (float)(WH - 2));
    float x0f = fminf(fmaxf(floorf(qx), 0.0f), (float)(WW - 2));
    float ay = fminf(fmaxf(qy - y0f, 0.0f), 1.0f);
    float ax = fminf(fmaxf(qx - x0f, 0.0f), 1.0f);

    int y0 = (int)y0f;
    int x0 = (int)x0f;

    const uint4* base = g_pair + ((size_t)b * (WH * WW) + (size_t)y0 * WW + x0);
    uint4 top = __ldg(base);         // taps (y0,x0),(y0,x0+1)   cache-normal
    uint4 bot = __ldg(base + WW);    // taps (y0+1,x0),(y0+1,x0+1)

    float2 t0 = h2f(top.x);
    float2 t1 = h2f(top.y);
    float2 t2 = h2f(top.z);
    float2 b0v = h2f(bot.x);
    float2 b1v = h2f(bot.y);
    float2 b2v = h2f(bot.z);

    float topr = t0.x + ax * (t1.y - t0.x);
    float topg = t0.y + ax * (t2.x - t0.y);
    float topb = t1.x + ax * (t2.y - t1.x);
    float botr = b0v.x + ax * (b1v.y - b0v.x);
    float botg = b0v.y + ax * (b2v.x - b0v.y);
    float botb = b1v.x + ax * (b2v.y - b1v.x);

    float* o = out + (size_t)idx * 3;
    __stcs(o + 0, topr + ay * (botr - topr));   // streaming stores
    __stcs(o + 1, topg + ay * (botg - topg));
    __stcs(o + 2, topb + ay * (botb - topb));
}

extern "C" void kernel_launch(void* const* d_in, const int* in_sizes, int n_in,
                              void* d_out, int out_size)
{
    const float* image = (const float*)d_in[0];
    const float* flow  = (const float*)d_in[1];
    float* out = (float*)d_out;

    const int threads = 256;
    const int blocks = (NPIX + threads - 1) / threads;

    pad_pair_kernel<<<blocks, threads>>>(image);
    warp_kernel<<<blocks, threads>>>(flow, out);
}

// round 13
// speedup vs baseline: 1.3875x; 1.2483x over previous
#include <cuda_runtime.h>
#include <cuda_fp16.h>
#include <cuda_bf16.h>

// dense_image_warp, B=8 H=1024 W=768 C=3 fp32 — single fused kernel.
// R13: each block owns a 64x64 output tile, cooperatively stages the
// (64+2*16+1)^2 input region in smem as fp16 rgbx (8B/px, 73.5KB), then
// gathers bilinear taps from smem (4x LDS.64/px). Queries outside the halo
// (|flow|>16, ~0.1%) fall back to direct fp32 gmem gathers.
// Eliminates the pad prepass (31us) and its 175MB of DRAM traffic + scratch.

#define WB 8
#define WH 1024
#define WW 768
#define TX 64
#define TY 64
#define HALO 16
#define IN_W (TX + 2 * HALO + 1)     // 97
#define IN_H (TY + 2 * HALO + 1)     // 97
#define NSM (IN_W * IN_H)            // 9409 slots * 8B = 75,272B
#define THREADS 512
#define PX_PER_T ((TX * TY) / THREADS)   // 8

__device__ __forceinline__ float2 h2f(unsigned u) {
    __half2 h = *reinterpret_cast<__half2*>(&u);
    return __half22float2(h);
}

__global__ void __launch_bounds__(THREADS) warp_tile_kernel(
    const float* __restrict__ img,
    const float* __restrict__ flow,
    float* __restrict__ out)
{
    extern __shared__ uint2 tile[];   // fp16 rgbx per pixel

    const int tid = threadIdx.x;
    const int b  = blockIdx.z;
    const int xs = blockIdx.x * TX - HALO;   // tile input origin (may be <0)
    const int ys = blockIdx.y * TY - HALO;

    const float* imgb = img + (size_t)b * (WH * WW * 3);

    // ---- cooperative tile load: gmem fp32 -> smem fp16 rgbx ----
    for (int l = tid; l < NSM; l += THREADS) {
        int sy = l / IN_W;
        int sx = l - sy * IN_W;
        int gx = min(max(xs + sx, 0), WW - 1);
        int gy = min(max(ys + sy, 0), WH - 1);
        const float* p = imgb + ((size_t)gy * WW + gx) * 3;
        float r = __ldg(p);
        float g = __ldg(p + 1);
        float bb = __ldg(p + 2);
        __half2 h0 = __floats2half2_rn(r, g);
        __half2 h1 = __floats2half2_rn(bb, 0.f);
        tile[l] = make_uint2(*reinterpret_cast<unsigned*>(&h0),
                             *reinterpret_cast<unsigned*>(&h1));
    }
    __syncthreads();

    // ---- gather + lerp, 8 px/thread ----
#pragma unroll
    for (int k = 0; k < PX_PER_T; k++) {
        int px = tid + k * THREADS;
        int ty = px >> 6;            // TX = 64
        int tx = px & 63;
        int oy = blockIdx.y * TY + ty;
        int ox = blockIdx.x * TX + tx;
        int idx = (b * WH + oy) * WW + ox;

        float2 f = __ldg(reinterpret_cast<const float2*>(flow) + idx);
        float qy = (float)oy - f.x;
        float qx = (float)ox - f.y;

        float y0f = fminf(fmaxf(floorf(qy), 0.0f), (float)(WH - 2));
        float x0f = fminf(fmaxf(floorf(qx), 0.0f), (float)(WW - 2));
        float ay = fminf(fmaxf(qy - y0f, 0.0f), 1.0f);
        float ax = fminf(fmaxf(qx - x0f, 0.0f), 1.0f);
        int y0 = (int)y0f;
        int x0 = (int)x0f;

        int sx = x0 - xs;
        int sy = y0 - ys;

        float tlr, tlg, tlb, trr, trg, trb;
        float blr, blg, blb, brr, brg, brb;

        if ((unsigned)sx < (IN_W - 1) && (unsigned)sy < (IN_H - 1)) {
            int s = sy * IN_W + sx;
            uint2 vtl = tile[s];
            uint2 vtr = tile[s + 1];
            uint2 vbl = tile[s + IN_W];
            uint2 vbr = tile[s + IN_W + 1];
            float2 a, c;
            a = h2f(vtl.x); c = h2f(vtl.y); tlr = a.x; tlg = a.y; tlb = c.x;
            a = h2f(vtr.x); c = h2f(vtr.y); trr = a.x; trg = a.y; trb = c.x;
            a = h2f(vbl.x); c = h2f(vbl.y); blr = a.x; blg = a.y; blb = c.x;
            a = h2f(vbr.x); c = h2f(vbr.y); brr = a.x; brg = a.y; brb = c.x;
        } else {
            // rare outlier: direct fp32 gmem taps
            const float* p0 = imgb + ((size_t)y0 * WW + x0) * 3;
            const float* p1 = p0 + (size_t)WW * 3;
            tlr = __ldg(p0);     tlg = __ldg(p0 + 1); tlb = __ldg(p0 + 2);
            trr = __ldg(p0 + 3); trg = __ldg(p0 + 4); trb = __ldg(p0 + 5);
            blr = __ldg(p1);     blg = __ldg(p1 + 1); blb = __ldg(p1 + 2);
            brr = __ldg(p1 + 3); brg = __ldg(p1 + 4); brb = __ldg(p1 + 5);
        }

        float topr = tlr + ax * (trr - tlr);
        float topg = tlg + ax * (trg - tlg);
        float topb = tlb + ax * (trb - tlb);
        float botr = blr + ax * (brr - blr);
        float botg = blg + ax * (brg - blg);
        float botb = blb + ax * (brb - blb);

        float* o = out + (size_t)idx * 3;
        o[0] = topr + ay * (botr - topr);
        o[1] = topg + ay * (botg - topg);
        o[2] = topb + ay * (botb - topb);
    }
}

extern "C" void kernel_launch(void* const* d_in, const int* in_sizes, int n_in,
                              void* d_out, int out_size)
{
    const float* image = (const float*)d_in[0];
    const float* flow  = (const float*)d_in[1];
    float* out = (float*)d_out;

    const int smem_bytes = NSM * sizeof(uint2);   // 75,272B > 48KB default
    cudaFuncSetAttribute(warp_tile_kernel,
                         cudaFuncAttributeMaxDynamicSharedMemorySize, smem_bytes);

    dim3 grid(WW / TX, WH / TY, WB);   // (12, 16, 8)
    warp_tile_kernel<<<grid, THREADS, smem_bytes>>>(image, flow, out);
}

// round 14
// speedup vs baseline: 1.4763x; 1.0639x over previous
#include <cuda_runtime.h>
#include <cuda_fp16.h>
#include <cuda_bf16.h>

// dense_image_warp, B=8 H=1024 W=768 C=3 fp32 — single fused kernel.
// R14: R13 tile-gather + issue/occupancy attack:
//  - 1024 threads/block, 4 adjacent px/thread (smem gather cost is
//    conflict-degree, NOT lines -> multi-px threads are free here):
//    2x LDG.128 flow, 3x STG.128 out, decode ALU amortized 4x.
//  - __launch_bounds__(1024,2): 2 blocks/SM * 1024 thr = 2048 = SM max (100% occ),
//    smem 2*75.3KB = 150.6KB fits 228KB.
//  - interior-block fast path skips per-slot coordinate clamping (73% of blocks).

#define WB 8
#define WH 1024
#define WW 768
#define TX 64
#define TY 64
#define HALO 16
#define IN_W (TX + 2 * HALO + 1)     // 97
#define IN_H (TY + 2 * HALO + 1)     // 97
#define NSM (IN_W * IN_H)            // 9409 slots * 8B = 75,272B
#define THREADS 1024

__device__ __forceinline__ float2 h2f(unsigned u) {
    __half2 h = *reinterpret_cast<__half2*>(&u);
    return __half22float2(h);
}

__device__ __forceinline__ uint2 pack_px(float r, float g, float b) {
    __half2 h0 = __floats2half2_rn(r, g);
    __half2 h1 = __floats2half2_rn(b, 0.f);
    return make_uint2(*reinterpret_cast<unsigned*>(&h0),
                      *reinterpret_cast<unsigned*>(&h1));
}

// one bilinear sample from smem tile (or rare gmem fallback), fp32 lerp
__device__ __forceinline__ void sample_px(
    const uint2* __restrict__ tile, const float* __restrict__ imgb,
    int xs, int ys, int oy, int ox, float2 f,
    float& orr, float& org, float& orb)
{
    float qy = (float)oy - f.x;
    float qx = (float)ox - f.y;
    float y0f = fminf(fmaxf(floorf(qy), 0.0f), (float)(WH - 2));
    float x0f = fminf(fmaxf(floorf(qx), 0.0f), (float)(WW - 2));
    float ay = fminf(fmaxf(qy - y0f, 0.0f), 1.0f);
    float ax = fminf(fmaxf(qx - x0f, 0.0f), 1.0f);
    int y0 = (int)y0f;
    int x0 = (int)x0f;
    int sx = x0 - xs;
    int sy = y0 - ys;

    float tlr, tlg, tlb, trr, trg, trb;
    float blr, blg, blb, brr, brg, brb;

    if ((unsigned)sx < (IN_W - 1) && (unsigned)sy < (IN_H - 1)) {
        int s = sy * IN_W + sx;
        uint2 vtl = tile[s];
        uint2 vtr = tile[s + 1];
        uint2 vbl = tile[s + IN_W];
        uint2 vbr = tile[s + IN_W + 1];
        float2 a, c;
        a = h2f(vtl.x); c = h2f(vtl.y); tlr = a.x; tlg = a.y; tlb = c.x;
        a = h2f(vtr.x); c = h2f(vtr.y); trr = a.x; trg = a.y; trb = c.x;
        a = h2f(vbl.x); c = h2f(vbl.y); blr = a.x; blg = a.y; blb = c.x;
        a = h2f(vbr.x); c = h2f(vbr.y); brr = a.x; brg = a.y; brb = c.x;
    } else {
        const float* p0 = imgb + ((size_t)y0 * WW + x0) * 3;
        const float* p1 = p0 + (size_t)WW * 3;
        tlr = __ldg(p0);     tlg = __ldg(p0 + 1); tlb = __ldg(p0 + 2);
        trr = __ldg(p0 + 3); trg = __ldg(p0 + 4); trb = __ldg(p0 + 5);
        blr = __ldg(p1);     blg = __ldg(p1 + 1); blb = __ldg(p1 + 2);
        brr = __ldg(p1 + 3); brg = __ldg(p1 + 4); brb = __ldg(p1 + 5);
    }

    float topr = tlr + ax * (trr - tlr);
    float topg = tlg + ax * (trg - tlg);
    float topb = tlb + ax * (trb - tlb);
    float botr = blr + ax * (brr - blr);
    float botg = blg + ax * (brg - blg);
    float botb = blb + ax * (brb - blb);
    orr = topr + ay * (botr - topr);
    org = topg + ay * (botg - topg);
    orb = topb + ay * (botb - topb);
}

__global__ void __launch_bounds__(THREADS, 2) warp_tile_kernel(
    const float* __restrict__ img,
    const float* __restrict__ flow,
    float* __restrict__ out)
{
    extern __shared__ uint2 tile[];   // fp16 rgbx per pixel

    const int tid = threadIdx.x;
    const int b  = blockIdx.z;
    const int xs = blockIdx.x * TX - HALO;
    const int ys = blockIdx.y * TY - HALO;

    const float* imgb = img + (size_t)b * (WH * WW * 3);

    // ---- cooperative tile load ----
    bool interior = (xs >= 0) && (ys >= 0) && (xs + IN_W <= WW) && (ys + IN_H <= WH);
    if (interior) {
        for (int l = tid; l < NSM; l += THREADS) {
            int sy = l / IN_W;
            int sx = l - sy * IN_W;
            const float* p = imgb + ((size_t)(ys + sy) * WW + (xs + sx)) * 3;
            tile[l] = pack_px(__ldg(p), __ldg(p + 1), __ldg(p + 2));
        }
    } else {
        for (int l = tid; l < NSM; l += THREADS) {
            int sy = l / IN_W;
            int sx = l - sy * IN_W;
            int gx = min(max(xs + sx, 0), WW - 1);
            int gy = min(max(ys + sy, 0), WH - 1);
            const float* p = imgb + ((size_t)gy * WW + gx) * 3;
            tile[l] = pack_px(__ldg(p), __ldg(p + 1), __ldg(p + 2));
        }
    }
    __syncthreads();

    // ---- gather + lerp: 4 adjacent px per thread (one quarter-row chunk) ----
    int row = tid >> 4;              // 16 chunks per 64-px row
    int col = (tid & 15) << 2;
    int oy = blockIdx.y * TY + row;
    int ox0 = blockIdx.x * TX + col;
    int idx0 = (b * WH + oy) * WW + ox0;

    const float4* fp = reinterpret_cast<const float4*>(flow) + (idx0 >> 1);
    float4 fA = __ldg(fp);           // px0: (dy,dx)=(x,y)  px1: (z,w)
    float4 fB = __ldg(fp + 1);       // px2, px3

    float r0, g0, b0, r1, g1, b1, r2, g2, b2, r3, g3, b3;
    sample_px(tile, imgb, xs, ys, oy, ox0 + 0, make_float2(fA.x, fA.y), r0, g0, b0);
    sample_px(tile, imgb, xs, ys, oy, ox0 + 1, make_float2(fA.z, fA.w), r1, g1, b1);
    sample_px(tile, imgb, xs, ys, oy, ox0 + 2, make_float2(fB.x, fB.y), r2, g2, b2);
    sample_px(tile, imgb, xs, ys, oy, ox0 + 3, make_float2(fB.z, fB.w), r3, g3, b3);

    float4* op = reinterpret_cast<float4*>(out + (size_t)idx0 * 3);
    op[0] = make_float4(r0, g0, b0, r1);
    op[1] = make_float4(g1, b1, r2, g2);
    op[2] = make_float4(b2, r3, g3, b3);
}

extern "C" void kernel_launch(void* const* d_in, const int* in_sizes, int n_in,
                              void* d_out, int out_size)
{
    const float* image = (const float*)d_in[0];
    const float* flow  = (const float*)d_in[1];
    float* out = (float*)d_out;

    const int smem_bytes = NSM * sizeof(uint2);   // 75,272B
    cudaFuncSetAttribute(warp_tile_kernel,
                         cudaFuncAttributeMaxDynamicSharedMemorySize, smem_bytes);

    dim3 grid(WW / TX, WH / TY, WB);   // (12, 16, 8)
    warp_tile_kernel<<<grid, THREADS, smem_bytes>>>(image, flow, out);
}